// round 15
// baseline (speedup 1.0000x reference)
#include <cuda_runtime.h>
#include <cuda_bf16.h>
#include <stdint.h>
#include <math.h>

// ---------------- problem constants ----------------
#define BB   2
#define TT   8192
#define DD   1024
#define HH   16
#define HD   64
#define CC   256
#define NC   (TT / CC)
#define BT   (BB * TT)          // 16384 rows
#define BH   (BB * HH)          // 32
#define NCH  (BH * NC)          // 1024
#define EPS  1e-6f

// ---------------- device scratch ----------------
__device__ float g_qkvg[BT * 4 * DD];
__device__ float g_qh[BT * DD];
__device__ float g_kh[BT * DD];
__device__ float g_vh[BT * DD];
__device__ float g_xtf[BT * DD];       // tf32-rounded x; reused later as "opre"
__device__ float g_wf[4 * DD * DD];    // tf32 TRANSPOSED fused weights [4N][K]
__device__ float g_wo[DD * DD];        // tf32 TRANSPOSED Wo [N][K]
__device__ float g_gt[BH * TT];
__device__ float g_bc[BH * TT];
__device__ float g_Bsum[NCH];
__device__ float g_kv[NCH * HD * HD];
__device__ float g_Sprev[NCH * HD * HD];

__device__ __forceinline__ float tf32r(float x) {
    uint32_t u;
    asm("cvt.rna.tf32.f32 %0, %1;" : "=r"(u) : "f"(x));
    return __uint_as_float(u);
}

#define MMA_TF32(acc, af, bf)                                              \
    asm volatile(                                                          \
        "mma.sync.aligned.m16n8k8.row.col.f32.tf32.tf32.f32 "              \
        "{%0,%1,%2,%3}, {%4,%5,%6,%7}, {%8,%9}, {%0,%1,%2,%3};\n"          \
        : "+f"((acc)[0]), "+f"((acc)[1]), "+f"((acc)[2]), "+f"((acc)[3])   \
        : "r"((af)[0]), "r"((af)[1]), "r"((af)[2]), "r"((af)[3]),          \
          "r"((bf)[0]), "r"((bf)[1]))

#define LDSM_X4(d, addr)                                                   \
    asm volatile(                                                          \
        "ldmatrix.sync.aligned.m8n8.x4.shared.b16 {%0,%1,%2,%3}, [%4];"    \
        : "=r"((d)[0]), "=r"((d)[1]), "=r"((d)[2]), "=r"((d)[3])           \
        : "r"(addr))

// ---------------- tf32 tensor-core GEMM (R10 best config): C = A @ Bt^T ----
#define BM  128
#define BN  256
#define BKK 32
#define STR 36
#define ASTG (BM * STR)
#define BSTG (BN * STR)
#define NSTAGE 3
#define SMEM_GEMM ((NSTAGE * (ASTG + BSTG)) * 4)   // 165888 B

__global__ __launch_bounds__(512, 1)
void gemm_tf32(const float* __restrict__ A, const float* __restrict__ Bt,
               float* __restrict__ C, int M, int N, int K) {
    extern __shared__ float sm[];
    float* As = sm;
    float* Bs = sm + NSTAGE * ASTG;

    const int tid  = threadIdx.x;
    const int wid  = tid >> 5, lane = tid & 31;
    const int wm   = wid >> 2, wn   = wid & 3;
    const int row0 = blockIdx.y * BM, col0 = blockIdx.x * BN;

    const int ar  = tid >> 2;
    const int akq = (tid & 3) * 8;
    const int br  = tid >> 1;
    const int bkq = (tid & 1) * 16;

    const float* Ag = A  + (size_t)(row0 + ar) * K + akq;
    const float* Bg = Bt + (size_t)(col0 + br) * K + bkq;

    uint32_t a_off[2];
#pragma unroll
    for (int mt = 0; mt < 2; mt++) {
        int r = wm * 32 + mt * 16 + ((lane >> 3) & 1) * 8 + (lane & 7);
        int c = (lane >> 4) * 4;
        a_off[mt] = (uint32_t)((r * STR + c) * 4);
    }
    uint32_t b_off[4];
#pragma unroll
    for (int j = 0; j < 4; j++) {
        int r = wn * 64 + j * 16 + ((lane >> 4) & 1) * 8 + (lane & 7);
        int c = ((lane >> 3) & 1) * 4;
        b_off[j] = (uint32_t)((r * STR + c) * 4);
    }
    const uint32_t sbA = (uint32_t)__cvta_generic_to_shared(As);
    const uint32_t sbB = (uint32_t)__cvta_generic_to_shared(Bs);

    float acc[2][8][4];
#pragma unroll
    for (int mt = 0; mt < 2; mt++)
#pragma unroll
        for (int nt = 0; nt < 8; nt++)
#pragma unroll
            for (int u = 0; u < 4; u++) acc[mt][nt][u] = 0.f;

    const int NIT = K / BKK;

#pragma unroll
    for (int s0 = 0; s0 < 2; s0++) {
        const int kt = s0 * BKK;
        uint32_t ab = (uint32_t)__cvta_generic_to_shared(
            &As[s0 * ASTG + ar * STR + akq]);
        uint32_t bb = (uint32_t)__cvta_generic_to_shared(
            &Bs[s0 * BSTG + br * STR + bkq]);
        const float* ag = Ag + kt;
        const float* bg = Bg + kt;
#pragma unroll
        for (int u = 0; u < 2; u++)
            asm volatile("cp.async.cg.shared.global [%0], [%1], 16;"
                         :: "r"(ab + u * 16), "l"(ag + u * 4));
#pragma unroll
        for (int u = 0; u < 4; u++)
            asm volatile("cp.async.cg.shared.global [%0], [%1], 16;"
                         :: "r"(bb + u * 16), "l"(bg + u * 4));
        asm volatile("cp.async.commit_group;");
    }

    int slot = 0;
    for (int it = 0; it < NIT; ++it) {
        if (it + 1 < NIT) {
            asm volatile("cp.async.wait_group 1;");
        } else {
            asm volatile("cp.async.wait_group 0;");
        }
        __syncthreads();

        if (it + 2 < NIT) {
            int ns = slot + 2; if (ns >= NSTAGE) ns -= NSTAGE;
            const int kt = (it + 2) * BKK;
            uint32_t ab = (uint32_t)__cvta_generic_to_shared(
                &As[ns * ASTG + ar * STR + akq]);
            uint32_t bb = (uint32_t)__cvta_generic_to_shared(
                &Bs[ns * BSTG + br * STR + bkq]);
            const float* ag = Ag + kt;
            const float* bg = Bg + kt;
#pragma unroll
            for (int u = 0; u < 2; u++)
                asm volatile("cp.async.cg.shared.global [%0], [%1], 16;"
                             :: "r"(ab + u * 16), "l"(ag + u * 4));
#pragma unroll
            for (int u = 0; u < 4; u++)
                asm volatile("cp.async.cg.shared.global [%0], [%1], 16;"
                             :: "r"(bb + u * 16), "l"(bg + u * 4));
            asm volatile("cp.async.commit_group;");
        }

        const uint32_t aS = sbA + slot * (ASTG * 4);
        const uint32_t bS = sbB + slot * (BSTG * 4);
#pragma unroll
        for (int ks = 0; ks < 4; ++ks) {
            const uint32_t ko = ks * 32;
            uint32_t af[2][4], bf[8][2];
#pragma unroll
            for (int mt = 0; mt < 2; mt++)
                LDSM_X4(af[mt], aS + a_off[mt] + ko);
#pragma unroll
            for (int j = 0; j < 4; j++) {
                uint32_t t4[4];
                LDSM_X4(t4, bS + b_off[j] + ko);
                bf[2 * j][0] = t4[0]; bf[2 * j][1] = t4[1];
                bf[2 * j + 1][0] = t4[2]; bf[2 * j + 1][1] = t4[3];
            }
#pragma unroll
            for (int mt = 0; mt < 2; mt++)
#pragma unroll
                for (int nt = 0; nt < 8; nt++)
                    MMA_TF32(acc[mt][nt], af[mt], bf[nt]);
        }
        if (++slot == NSTAGE) slot = 0;
    }

    const int crow = row0 + wm * 32 + (lane >> 2);
    const int ccol = col0 + wn * 64 + (lane & 3) * 2;
#pragma unroll
    for (int mt = 0; mt < 2; mt++)
#pragma unroll
        for (int nt = 0; nt < 8; nt++) {
            float* p0 = C + (size_t)(crow + mt * 16) * N + ccol + nt * 8;
            float* p1 = p0 + (size_t)8 * N;
            *(float2*)p0 = make_float2(acc[mt][nt][0], acc[mt][nt][1]);
            *(float2*)p1 = make_float2(acc[mt][nt][2], acc[mt][nt][3]);
        }
}

// ---------------- tensorized attention (unchanged from 1824us best) -------------
#define PSTR 68
#define SMEM_ATTN ((256 * PSTR + 64 * PSTR + 64 * PSTR + 8 * 32 * PSTR) * 4)

__global__ __launch_bounds__(256, 1)
void attn_mma(const float* __restrict__ qh, const float* __restrict__ kh,
              const float* __restrict__ vh, const float* __restrict__ bc,
              const float* __restrict__ Sprev, const float* __restrict__ gate,
              float* __restrict__ opre) {
    extern __shared__ float sm[];
    float* qs  = sm;
    float* bsK = qs + 256 * PSTR;
    float* bsV = bsK + 64 * PSTR;
    float* Pw  = bsV + 64 * PSTR;

    const int cid = blockIdx.x;
    const int bh = cid / NC, n = cid % NC;
    const int b = bh / HH, h = bh % HH;
    const int tid = threadIdx.x;
    const int w = tid >> 5, lane = tid & 31;
    const size_t tbase = (size_t)bh * TT + n * CC;

    {
        const int r = tid;
        const float ebc = expf(bc[tbase + r]);
        const float4* qp = (const float4*)&qh[(tbase + r) * HD];
#pragma unroll
        for (int g = 0; g < 16; g++) {
            float4 q = qp[g];
            q.x = tf32r(q.x * ebc); q.y = tf32r(q.y * ebc);
            q.z = tf32r(q.z * ebc); q.w = tf32r(q.w * ebc);
            *(float4*)&qs[r * PSTR + g * 4] = q;
        }
    }
    {
        const int e = tid & 63, dg = (tid >> 6) * 16;
        const float* Sp = Sprev + (size_t)cid * HD * HD;
#pragma unroll
        for (int i = 0; i < 16; i++)
            bsK[e * PSTR + dg + i] = tf32r(Sp[(dg + i) * HD + e]);
    }
    __syncthreads();

    uint32_t a_offQ[2], a_offP[2], b_off[4];
#pragma unroll
    for (int mt = 0; mt < 2; mt++) {
        int rr = mt * 16 + ((lane >> 3) & 1) * 8 + (lane & 7);
        int cc = (lane >> 4) * 4;
        a_offQ[mt] = (uint32_t)(((w * 32 + rr) * PSTR + cc) * 4);
        a_offP[mt] = (uint32_t)((w * 32 * PSTR + rr * PSTR + cc) * 4);
    }
#pragma unroll
    for (int j = 0; j < 4; j++) {
        int rr = j * 16 + ((lane >> 4) & 1) * 8 + (lane & 7);
        int cc = ((lane >> 3) & 1) * 4;
        b_off[j] = (uint32_t)((rr * PSTR + cc) * 4);
    }
    const uint32_t sQ = (uint32_t)__cvta_generic_to_shared(qs);
    const uint32_t sK = (uint32_t)__cvta_generic_to_shared(bsK);
    const uint32_t sV = (uint32_t)__cvta_generic_to_shared(bsV);
    const uint32_t sP = (uint32_t)__cvta_generic_to_shared(Pw);

    float O[2][8][4];
#pragma unroll
    for (int mt = 0; mt < 2; mt++)
#pragma unroll
        for (int nt = 0; nt < 8; nt++)
#pragma unroll
            for (int u = 0; u < 4; u++) O[mt][nt][u] = 0.f;

#pragma unroll
    for (int ks = 0; ks < 8; ++ks) {
        const uint32_t ko = ks * 32;
        uint32_t af[2][4], bf[8][2];
#pragma unroll
        for (int mt = 0; mt < 2; mt++) LDSM_X4(af[mt], sQ + a_offQ[mt] + ko);
#pragma unroll
        for (int j = 0; j < 4; j++) {
            uint32_t t4[4];
            LDSM_X4(t4, sK + b_off[j] + ko);
            bf[2 * j][0] = t4[0]; bf[2 * j][1] = t4[1];
            bf[2 * j + 1][0] = t4[2]; bf[2 * j + 1][1] = t4[3];
        }
#pragma unroll
        for (int mt = 0; mt < 2; mt++)
#pragma unroll
            for (int nt = 0; nt < 8; nt++)
                MMA_TF32(O[mt][nt], af[mt], bf[nt]);
    }

    const int jmax = w >> 1;
    for (int j = 0; j < 4; ++j) {
        __syncthreads();
        {
            const int c = tid >> 2, cg = (tid & 3) * 16;
            const float em = expf(-bc[tbase + j * 64 + c]);
            const float4* kp = (const float4*)&kh[(tbase + j * 64 + c) * HD + cg];
#pragma unroll
            for (int ii = 0; ii < 4; ii++) {
                float4 k4 = kp[ii];
                k4.x = tf32r(k4.x * em); k4.y = tf32r(k4.y * em);
                k4.z = tf32r(k4.z * em); k4.w = tf32r(k4.w * em);
                *(float4*)&bsK[c * PSTR + cg + ii * 4] = k4;
            }
        }
        {
            const int c = tid & 63, dg = (tid >> 6) * 16;
            const float4* vp = (const float4*)&vh[(tbase + j * 64 + c) * HD + dg];
#pragma unroll
            for (int ii = 0; ii < 4; ii++) {
                float4 v4 = vp[ii];
                bsV[(dg + ii * 4 + 0) * PSTR + c] = tf32r(v4.x);
                bsV[(dg + ii * 4 + 1) * PSTR + c] = tf32r(v4.y);
                bsV[(dg + ii * 4 + 2) * PSTR + c] = tf32r(v4.z);
                bsV[(dg + ii * 4 + 3) * PSTR + c] = tf32r(v4.w);
            }
        }
        __syncthreads();

        if (j <= jmax) {
            float P[2][8][4];
#pragma unroll
            for (int mt = 0; mt < 2; mt++)
#pragma unroll
                for (int nt = 0; nt < 8; nt++)
#pragma unroll
                    for (int u = 0; u < 4; u++) P[mt][nt][u] = 0.f;
#pragma unroll
            for (int ks = 0; ks < 8; ++ks) {
                const uint32_t ko = ks * 32;
                uint32_t af[2][4], bf[8][2];
#pragma unroll
                for (int mt = 0; mt < 2; mt++)
                    LDSM_X4(af[mt], sQ + a_offQ[mt] + ko);
#pragma unroll
                for (int jj = 0; jj < 4; jj++) {
                    uint32_t t4[4];
                    LDSM_X4(t4, sK + b_off[jj] + ko);
                    bf[2 * jj][0] = t4[0]; bf[2 * jj][1] = t4[1];
                    bf[2 * jj + 1][0] = t4[2]; bf[2 * jj + 1][1] = t4[3];
                }
#pragma unroll
                for (int mt = 0; mt < 2; mt++)
#pragma unroll
                    for (int nt = 0; nt < 8; nt++)
                        MMA_TF32(P[mt][nt], af[mt], bf[nt]);
            }
            const bool diag = (j == jmax);
            const int rbase = (w & 1) * 32;
            float* Pm = Pw + w * 32 * PSTR;
#pragma unroll
            for (int mt = 0; mt < 2; mt++)
#pragma unroll
                for (int nt = 0; nt < 8; nt++)
#pragma unroll
                    for (int u = 0; u < 4; u++) {
                        int rl = mt * 16 + (lane >> 2) + ((u >> 1) << 3);
                        int cl = nt * 8 + 2 * (lane & 3) + (u & 1);
                        float val = P[mt][nt][u];
                        if (diag && (rbase + rl) < cl) val = 0.f;
                        Pm[rl * PSTR + cl] = tf32r(val);
                    }
            __syncwarp();
#pragma unroll
            for (int ks = 0; ks < 8; ++ks) {
                const uint32_t ko = ks * 32;
                uint32_t af[2][4], bf[8][2];
#pragma unroll
                for (int mt = 0; mt < 2; mt++)
                    LDSM_X4(af[mt], sP + a_offP[mt] + ko);
#pragma unroll
                for (int jj = 0; jj < 4; jj++) {
                    uint32_t t4[4];
                    LDSM_X4(t4, sV + b_off[jj] + ko);
                    bf[2 * jj][0] = t4[0]; bf[2 * jj][1] = t4[1];
                    bf[2 * jj + 1][0] = t4[2]; bf[2 * jj + 1][1] = t4[3];
                }
#pragma unroll
                for (int mt = 0; mt < 2; mt++)
#pragma unroll
                    for (int nt = 0; nt < 8; nt++)
                        MMA_TF32(O[mt][nt], af[mt], bf[nt]);
            }
        }
    }

#pragma unroll
    for (int mt = 0; mt < 2; mt++) {
        float s0 = 0.f, s1 = 0.f;
#pragma unroll
        for (int nt = 0; nt < 8; nt++) {
            s0 += O[mt][nt][0] * O[mt][nt][0] + O[mt][nt][1] * O[mt][nt][1];
            s1 += O[mt][nt][2] * O[mt][nt][2] + O[mt][nt][3] * O[mt][nt][3];
        }
        s0 += __shfl_xor_sync(0xffffffffu, s0, 1);
        s0 += __shfl_xor_sync(0xffffffffu, s0, 2);
        s1 += __shfl_xor_sync(0xffffffffu, s1, 1);
        s1 += __shfl_xor_sync(0xffffffffu, s1, 2);
        const float rr0 = rsqrtf(s0 * (1.f / (float)HD) + EPS);
        const float rr1 = rsqrtf(s1 * (1.f / (float)HD) + EPS);

        const int lr0 = w * 32 + mt * 16 + (lane >> 2);
        const size_t row0 = (size_t)b * TT + n * CC + lr0;
        const size_t row1 = row0 + 8;
#pragma unroll
        for (int nt = 0; nt < 8; nt++) {
            const int c0 = h * HD + nt * 8 + 2 * (lane & 3);
            float2 ga = *(const float2*)&gate[row0 * (4 * DD) + 3 * DD + c0];
            float2 gb = *(const float2*)&gate[row1 * (4 * DD) + 3 * DD + c0];
            float sax = ga.x / (1.f + expf(-ga.x));
            float say = ga.y / (1.f + expf(-ga.y));
            float sbx = gb.x / (1.f + expf(-gb.x));
            float sby = gb.y / (1.f + expf(-gb.y));
            *(float2*)&opre[row0 * DD + c0] = make_float2(
                tf32r(sax * O[mt][nt][0] * rr0), tf32r(say * O[mt][nt][1] * rr0));
            *(float2*)&opre[row1 * DD + c0] = make_float2(
                tf32r(sbx * O[mt][nt][2] * rr1), tf32r(sby * O[mt][nt][3] * rr1));
        }
    }
}

// ---------------- prep: round x to tf32 ----------------
__global__ __launch_bounds__(256)
void round_tf32(const float* __restrict__ in, float* __restrict__ out) {
    size_t i = ((size_t)blockIdx.x * 256 + threadIdx.x) * 4;
    float4 v = *(const float4*)(in + i);
    v.x = tf32r(v.x); v.y = tf32r(v.y); v.z = tf32r(v.z); v.w = tf32r(v.w);
    *(float4*)(out + i) = v;
}

// ---------------- prep: transpose + round 5 weights -> [N][K] (batched) ----------
__global__ __launch_bounds__(256)
void round_tr5(const float* __restrict__ Wq, const float* __restrict__ Wk,
               const float* __restrict__ Wv, const float* __restrict__ Wg,
               const float* __restrict__ Wo,
               float* __restrict__ Wf, float* __restrict__ WoT) {
    __shared__ float t[32][33];
    const float* srcs[5] = {Wq, Wk, Wv, Wg, Wo};
    const int z = blockIdx.z;
    const float* W = srcs[z];
    float* Wt = (z < 4) ? (Wf + (size_t)z * DD * DD) : WoT;
    const int bx = blockIdx.x * 32, by = blockIdx.y * 32;
    const int x = threadIdx.x & 31, y = threadIdx.x >> 5;
#pragma unroll
    for (int j = 0; j < 32; j += 8)
        t[y + j][x] = W[(size_t)(by + y + j) * DD + bx + x];
    __syncthreads();
#pragma unroll
    for (int j = 0; j < 32; j += 8)
        Wt[(size_t)(bx + y + j) * DD + by + x] = tf32r(t[x][y + j]);
}

// ---------------- skinny GEMM (vectorized): gt = log_sigmoid(x @ Wgt)/16 -------
// wsT smem layout [16][WTS]: stride 1028 -> the 16 float4-readers per phase hit
// disjoint bank quads (1028 % 32 == 4). xs reads broadcast across 16 lanes.
#define WTS 1028
#define GT_SMEM ((16 * WTS + 16 * 68) * 4)   // 70144 B

__global__ __launch_bounds__(256)
void gt_gemm(const float* __restrict__ x, const float* __restrict__ Wgt,
             float* __restrict__ gtout) {
    extern __shared__ float smg[];
    float* wsT = smg;               // [16][WTS]  (Wgt transposed)
    float* xs  = smg + 16 * WTS;    // [16][68]
    const int row0 = blockIdx.x * 16;
    const int tid = threadIdx.x;
    const int r = tid >> 4, c = tid & 15;

    // stage Wgt transposed: read coalesced, scatter to wsT[c][k]
    for (int idx = tid; idx < DD * HH; idx += 256) {
        int k = idx >> 4, cc = idx & 15;
        wsT[cc * WTS + k] = Wgt[idx];
    }

    const int lr = tid >> 4, lc = (tid & 15) * 4;
    float acc = 0.f;
    for (int kt = 0; kt < DD; kt += 64) {
        __syncthreads();
        *(float4*)&xs[lr * 68 + lc] =
            *(const float4*)&x[(size_t)(row0 + lr) * DD + kt + lc];
        __syncthreads();
#pragma unroll
        for (int kk = 0; kk < 64; kk += 4) {
            float4 a = *(const float4*)&xs[r * 68 + kk];
            float4 b = *(const float4*)&wsT[c * WTS + kt + kk];
            acc += a.x * b.x + a.y * b.y + a.z * b.z + a.w * b.w;
        }
    }
    float z = acc;
    float ls = fminf(z, 0.f) - log1pf(expf(-fabsf(z)));
    int row = row0 + r;
    int b = row / TT, t = row % TT;
    gtout[((size_t)(b * HH + c)) * TT + t] = ls * (1.f / 16.f);
}

// ---------------- fused rmsnorm (q,k,v) + reorder to head-major ----------
__global__ __launch_bounds__(256)
void rmsnorm_reorder3(const float* __restrict__ qkvg, float* __restrict__ qd,
                      float* __restrict__ kd, float* __restrict__ vd) {
    const int row = blockIdx.x;
    const int b = row / TT, t = row % TT;
    const int tid = threadIdx.x;
    __shared__ float red[8];
    float* dsts[3] = {qd, kd, vd};
    const float extras[3] = {0.125f, 1.f, 1.f};
#pragma unroll
    for (int part = 0; part < 3; part++) {
        float4 v = *(const float4*)&qkvg[(size_t)row * (4 * DD) + part * DD + tid * 4];
        float ss = v.x * v.x + v.y * v.y + v.z * v.z + v.w * v.w;
#pragma unroll
        for (int off = 16; off > 0; off >>= 1)
            ss += __shfl_xor_sync(0xffffffffu, ss, off);
        if ((tid & 31) == 0) red[tid >> 5] = ss;
        __syncthreads();
        float tot = red[0] + red[1] + red[2] + red[3] +
                    red[4] + red[5] + red[6] + red[7];
        float rr = rsqrtf(tot * (1.f / (float)DD) + EPS) * extras[part];
        int col = tid * 4;
        int h = col >> 6, j = col & 63;
        *(float4*)&dsts[part][((size_t)(b * HH + h) * TT + t) * HD + j] =
            make_float4(v.x * rr, v.y * rr, v.z * rr, v.w * rr);
        __syncthreads();
    }
}

// ---------------- per-chunk inclusive cumsum of gt ----------------
__global__ __launch_bounds__(256)
void cumsum_kernel(const float* __restrict__ gt, float* __restrict__ bc,
                   float* __restrict__ Bsum) {
    const int cid = blockIdx.x;
    const int bh = cid / NC, n = cid % NC;
    const int i = threadIdx.x;
    const size_t idx = (size_t)bh * TT + n * CC + i;
    __shared__ float s[CC];
    s[i] = gt[idx];
    __syncthreads();
    for (int off = 1; off < CC; off <<= 1) {
        float add = (i >= off) ? s[i - off] : 0.f;
        __syncthreads();
        s[i] += add;
        __syncthreads();
    }
    bc[idx] = s[i];
    if (i == CC - 1) Bsum[cid] = s[i];
}

// ---------------- per-chunk kv = (k * exp(B - bc))^T @ v  (64x64) ----------------
__global__ __launch_bounds__(256)
void kv_kernel(const float* __restrict__ kh, const float* __restrict__ vh,
               const float* __restrict__ bc, const float* __restrict__ Bsum,
               float* __restrict__ kv) {
    const int cid = blockIdx.x;
    const int bh = cid / NC, n = cid % NC;
    const size_t tbase = (size_t)bh * TT + n * CC;
    const int tid = threadIdx.x;
    __shared__ float ks[32][64];
    __shared__ float vs[32][64];
    const float Bn = Bsum[cid];
    const int ty = tid >> 4, tx = tid & 15;
    const int tr = tid >> 3, c8 = (tid & 7) << 3;
    float acc[4][4];
#pragma unroll
    for (int i = 0; i < 4; i++)
#pragma unroll
        for (int j = 0; j < 4; j++) acc[i][j] = 0.f;

    for (int ct = 0; ct < 8; ++ct) {
        __syncthreads();
        int trow = ct * 32 + tr;
        float e = expf(Bn - bc[tbase + trow]);
        size_t gb = (tbase + trow) * HD;
        float4 k0 = *(const float4*)&kh[gb + c8];
        float4 k1 = *(const float4*)&kh[gb + c8 + 4];
        *(float4*)&ks[tr][c8]     = make_float4(k0.x * e, k0.y * e, k0.z * e, k0.w * e);
        *(float4*)&ks[tr][c8 + 4] = make_float4(k1.x * e, k1.y * e, k1.z * e, k1.w * e);
        *(float4*)&vs[tr][c8]     = *(const float4*)&vh[gb + c8];
        *(float4*)&vs[tr][c8 + 4] = *(const float4*)&vh[gb + c8 + 4];
        __syncthreads();
#pragma unroll
        for (int kk = 0; kk < 32; ++kk) {
            float4 ka = *(const float4*)&ks[kk][ty * 4];
            float4 vb = *(const float4*)&vs[kk][tx * 4];
            float kaa[4] = {ka.x, ka.y, ka.z, ka.w};
            float vbb[4] = {vb.x, vb.y, vb.z, vb.w};
#pragma unroll
            for (int i = 0; i < 4; i++)
#pragma unroll
                for (int j = 0; j < 4; j++)
                    acc[i][j] += kaa[i] * vbb[j];
        }
    }
    size_t ob = (size_t)cid * HD * HD;
#pragma unroll
    for (int i = 0; i < 4; i++)
        *(float4*)&kv[ob + (size_t)(ty * 4 + i) * HD + tx * 4] =
            make_float4(acc[i][0], acc[i][1], acc[i][2], acc[i][3]);
}

// ---------------- sequential chunk scan ----------------
__global__ __launch_bounds__(256)
void scan_kernel(const float* __restrict__ kv, const float* __restrict__ Bsum,
                 float* __restrict__ Sprev) {
    const int bh = blockIdx.x;
    const int tid = threadIdx.x;
    float4 S[4];
#pragma unroll
    for (int u = 0; u < 4; u++) S[u] = make_float4(0.f, 0.f, 0.f, 0.f);
    for (int n = 0; n < NC; ++n) {
        size_t cb = (size_t)(bh * NC + n) * HD * HD + tid * 16;
#pragma unroll
        for (int u = 0; u < 4; u++) *(float4*)&Sprev[cb + u * 4] = S[u];
        float eB = expf(Bsum[bh * NC + n]);
#pragma unroll
        for (int u = 0; u < 4; u++) {
            float4 kvv = *(const float4*)&kv[cb + u * 4];
            S[u].x = eB * S[u].x + kvv.x;
            S[u].y = eB * S[u].y + kvv.y;
            S[u].z = eB * S[u].z + kvv.z;
            S[u].w = eB * S[u].w + kvv.w;
        }
    }
}

// ---------------- host launcher ----------------
static float* devptr(const void* symbol) {
    void* p = nullptr;
    cudaGetSymbolAddress(&p, symbol);
    return (float*)p;
}

extern "C" void kernel_launch(void* const* d_in, const int* in_sizes, int n_in,
                              void* d_out, int out_size) {
    const float* x   = (const float*)d_in[0];
    const float* Wq  = (const float*)d_in[1];
    const float* Wk  = (const float*)d_in[2];
    const float* Wv  = (const float*)d_in[3];
    const float* Wg  = (const float*)d_in[4];
    const float* Wgt = (const float*)d_in[5];
    const float* Wo  = (const float*)d_in[6];
    float* out = (float*)d_out;

    float* qkvg = devptr(g_qkvg);
    float* qhp = devptr(g_qh);
    float* khp = devptr(g_kh);
    float* vhp = devptr(g_vh);
    float* xtf = devptr(g_xtf);
    float* wf  = devptr(g_wf);
    float* wo  = devptr(g_wo);
    float* gtp = devptr(g_gt);
    float* bcp = devptr(g_bc);
    float* Bp  = devptr(g_Bsum);
    float* kvp = devptr(g_kv);
    float* Sp  = devptr(g_Sprev);

    cudaFuncSetAttribute(gemm_tf32,
        cudaFuncAttributeMaxDynamicSharedMemorySize, SMEM_GEMM);
    cudaFuncSetAttribute(attn_mma,
        cudaFuncAttributeMaxDynamicSharedMemorySize, SMEM_ATTN);
    cudaFuncSetAttribute(gt_gemm,
        cudaFuncAttributeMaxDynamicSharedMemorySize, GT_SMEM);

    // prep
    round_tf32<<<(BT * DD / 4) / 256, 256>>>(x, xtf);
    dim3 tg5(32, 32, 5);
    round_tr5<<<tg5, 256>>>(Wq, Wk, Wv, Wg, Wo, wf, wo);

    dim3 gfused(4 * DD / BN, BT / BM);   // (16, 128)
    gemm_tf32<<<gfused, 512, SMEM_GEMM>>>(xtf, wf, qkvg, BT, 4 * DD, DD);
    gt_gemm<<<BT / 16, 256, GT_SMEM>>>(x, Wgt, gtp);

    rmsnorm_reorder3<<<BT, 256>>>(qkvg, qhp, khp, vhp);

    cumsum_kernel<<<NCH, 256>>>(gtp, bcp, Bp);
    kv_kernel<<<NCH, 256>>>(khp, vhp, bcp, Bp, kvp);
    scan_kernel<<<BH, 256>>>(kvp, Bp, Sp);

    // xtf dead after fused GEMM: reuse as opre
    attn_mma<<<NCH, 256, SMEM_ATTN>>>(qhp, khp, vhp, bcp, Sp, qkvg, xtf);

    dim3 gout(DD / BN, BT / BM);         // (4, 128)
    gemm_tf32<<<gout, 512, SMEM_GEMM>>>(xtf, wo, out, BT, DD, DD);
}

// round 16
// speedup vs baseline: 1.0190x; 1.0190x over previous
#include <cuda_runtime.h>
#include <cuda_bf16.h>
#include <stdint.h>
#include <math.h>

// ---------------- problem constants ----------------
#define BB   2
#define TT   8192
#define DD   1024
#define HH   16
#define HD   64
#define CC   256
#define NC   (TT / CC)
#define BT   (BB * TT)          // 16384 rows
#define BH   (BB * HH)          // 32
#define NCH  (BH * NC)          // 1024
#define EPS  1e-6f

// ---------------- device scratch ----------------
__device__ float g_qkvg[BT * 4 * DD];
__device__ float g_qh[BT * DD];
__device__ float g_kh[BT * DD];
__device__ float g_vh[BT * DD];
__device__ float g_xtf[BT * DD];       // tf32-rounded x; reused later as "opre"
__device__ float g_wf[4 * DD * DD];    // tf32 TRANSPOSED fused weights [4N][K]
__device__ float g_wo[DD * DD];        // tf32 TRANSPOSED Wo [N][K]
__device__ float g_gt[BH * TT];
__device__ float g_bc[BH * TT];
__device__ float g_Bsum[NCH];
__device__ float g_kv[NCH * HD * HD];
__device__ float g_Sprev[NCH * HD * HD];

__device__ __forceinline__ float tf32r(float x) {
    uint32_t u;
    asm("cvt.rna.tf32.f32 %0, %1;" : "=r"(u) : "f"(x));
    return __uint_as_float(u);
}

#define MMA_TF32(acc, af, bf)                                              \
    asm volatile(                                                          \
        "mma.sync.aligned.m16n8k8.row.col.f32.tf32.tf32.f32 "              \
        "{%0,%1,%2,%3}, {%4,%5,%6,%7}, {%8,%9}, {%0,%1,%2,%3};\n"          \
        : "+f"((acc)[0]), "+f"((acc)[1]), "+f"((acc)[2]), "+f"((acc)[3])   \
        : "r"((af)[0]), "r"((af)[1]), "r"((af)[2]), "r"((af)[3]),          \
          "r"((bf)[0]), "r"((bf)[1]))

#define LDSM_X4(d, addr)                                                   \
    asm volatile(                                                          \
        "ldmatrix.sync.aligned.m8n8.x4.shared.b16 {%0,%1,%2,%3}, [%4];"    \
        : "=r"((d)[0]), "=r"((d)[1]), "=r"((d)[2]), "=r"((d)[3])           \
        : "r"(addr))

// ---------------- tf32 tensor-core GEMM (R10 best config): C = A @ Bt^T ----
#define BM  128
#define BN  256
#define BKK 32
#define STR 36
#define ASTG (BM * STR)
#define BSTG (BN * STR)
#define NSTAGE 3
#define SMEM_GEMM ((NSTAGE * (ASTG + BSTG)) * 4)   // 165888 B

__global__ __launch_bounds__(512, 1)
void gemm_tf32(const float* __restrict__ A, const float* __restrict__ Bt,
               float* __restrict__ C, int M, int N, int K) {
    extern __shared__ float sm[];
    float* As = sm;
    float* Bs = sm + NSTAGE * ASTG;

    const int tid  = threadIdx.x;
    const int wid  = tid >> 5, lane = tid & 31;
    const int wm   = wid >> 2, wn   = wid & 3;
    const int row0 = blockIdx.y * BM, col0 = blockIdx.x * BN;

    const int ar  = tid >> 2;
    const int akq = (tid & 3) * 8;
    const int br  = tid >> 1;
    const int bkq = (tid & 1) * 16;

    const float* Ag = A  + (size_t)(row0 + ar) * K + akq;
    const float* Bg = Bt + (size_t)(col0 + br) * K + bkq;

    uint32_t a_off[2];
#pragma unroll
    for (int mt = 0; mt < 2; mt++) {
        int r = wm * 32 + mt * 16 + ((lane >> 3) & 1) * 8 + (lane & 7);
        int c = (lane >> 4) * 4;
        a_off[mt] = (uint32_t)((r * STR + c) * 4);
    }
    uint32_t b_off[4];
#pragma unroll
    for (int j = 0; j < 4; j++) {
        int r = wn * 64 + j * 16 + ((lane >> 4) & 1) * 8 + (lane & 7);
        int c = ((lane >> 3) & 1) * 4;
        b_off[j] = (uint32_t)((r * STR + c) * 4);
    }
    const uint32_t sbA = (uint32_t)__cvta_generic_to_shared(As);
    const uint32_t sbB = (uint32_t)__cvta_generic_to_shared(Bs);

    float acc[2][8][4];
#pragma unroll
    for (int mt = 0; mt < 2; mt++)
#pragma unroll
        for (int nt = 0; nt < 8; nt++)
#pragma unroll
            for (int u = 0; u < 4; u++) acc[mt][nt][u] = 0.f;

    const int NIT = K / BKK;

#pragma unroll
    for (int s0 = 0; s0 < 2; s0++) {
        const int kt = s0 * BKK;
        uint32_t ab = (uint32_t)__cvta_generic_to_shared(
            &As[s0 * ASTG + ar * STR + akq]);
        uint32_t bb = (uint32_t)__cvta_generic_to_shared(
            &Bs[s0 * BSTG + br * STR + bkq]);
        const float* ag = Ag + kt;
        const float* bg = Bg + kt;
#pragma unroll
        for (int u = 0; u < 2; u++)
            asm volatile("cp.async.cg.shared.global [%0], [%1], 16;"
                         :: "r"(ab + u * 16), "l"(ag + u * 4));
#pragma unroll
        for (int u = 0; u < 4; u++)
            asm volatile("cp.async.cg.shared.global [%0], [%1], 16;"
                         :: "r"(bb + u * 16), "l"(bg + u * 4));
        asm volatile("cp.async.commit_group;");
    }

    int slot = 0;
    for (int it = 0; it < NIT; ++it) {
        if (it + 1 < NIT) {
            asm volatile("cp.async.wait_group 1;");
        } else {
            asm volatile("cp.async.wait_group 0;");
        }
        __syncthreads();

        if (it + 2 < NIT) {
            int ns = slot + 2; if (ns >= NSTAGE) ns -= NSTAGE;
            const int kt = (it + 2) * BKK;
            uint32_t ab = (uint32_t)__cvta_generic_to_shared(
                &As[ns * ASTG + ar * STR + akq]);
            uint32_t bb = (uint32_t)__cvta_generic_to_shared(
                &Bs[ns * BSTG + br * STR + bkq]);
            const float* ag = Ag + kt;
            const float* bg = Bg + kt;
#pragma unroll
            for (int u = 0; u < 2; u++)
                asm volatile("cp.async.cg.shared.global [%0], [%1], 16;"
                             :: "r"(ab + u * 16), "l"(ag + u * 4));
#pragma unroll
            for (int u = 0; u < 4; u++)
                asm volatile("cp.async.cg.shared.global [%0], [%1], 16;"
                             :: "r"(bb + u * 16), "l"(bg + u * 4));
            asm volatile("cp.async.commit_group;");
        }

        const uint32_t aS = sbA + slot * (ASTG * 4);
        const uint32_t bS = sbB + slot * (BSTG * 4);
#pragma unroll
        for (int ks = 0; ks < 4; ++ks) {
            const uint32_t ko = ks * 32;
            uint32_t af[2][4], bf[8][2];
#pragma unroll
            for (int mt = 0; mt < 2; mt++)
                LDSM_X4(af[mt], aS + a_off[mt] + ko);
#pragma unroll
            for (int j = 0; j < 4; j++) {
                uint32_t t4[4];
                LDSM_X4(t4, bS + b_off[j] + ko);
                bf[2 * j][0] = t4[0]; bf[2 * j][1] = t4[1];
                bf[2 * j + 1][0] = t4[2]; bf[2 * j + 1][1] = t4[3];
            }
#pragma unroll
            for (int mt = 0; mt < 2; mt++)
#pragma unroll
                for (int nt = 0; nt < 8; nt++)
                    MMA_TF32(acc[mt][nt], af[mt], bf[nt]);
        }
        if (++slot == NSTAGE) slot = 0;
    }

    const int crow = row0 + wm * 32 + (lane >> 2);
    const int ccol = col0 + wn * 64 + (lane & 3) * 2;
#pragma unroll
    for (int mt = 0; mt < 2; mt++)
#pragma unroll
        for (int nt = 0; nt < 8; nt++) {
            float* p0 = C + (size_t)(crow + mt * 16) * N + ccol + nt * 8;
            float* p1 = p0 + (size_t)8 * N;
            *(float2*)p0 = make_float2(acc[mt][nt][0], acc[mt][nt][1]);
            *(float2*)p1 = make_float2(acc[mt][nt][2], acc[mt][nt][3]);
        }
}

// ---------------- tensorized attention (unchanged from 1824us best) -------------
#define PSTR 68
#define SMEM_ATTN ((256 * PSTR + 64 * PSTR + 64 * PSTR + 8 * 32 * PSTR) * 4)

__global__ __launch_bounds__(256, 1)
void attn_mma(const float* __restrict__ qh, const float* __restrict__ kh,
              const float* __restrict__ vh, const float* __restrict__ bc,
              const float* __restrict__ Sprev, const float* __restrict__ gate,
              float* __restrict__ opre) {
    extern __shared__ float sm[];
    float* qs  = sm;
    float* bsK = qs + 256 * PSTR;
    float* bsV = bsK + 64 * PSTR;
    float* Pw  = bsV + 64 * PSTR;

    const int cid = blockIdx.x;
    const int bh = cid / NC, n = cid % NC;
    const int b = bh / HH, h = bh % HH;
    const int tid = threadIdx.x;
    const int w = tid >> 5, lane = tid & 31;
    const size_t tbase = (size_t)bh * TT + n * CC;

    {
        const int r = tid;
        const float ebc = expf(bc[tbase + r]);
        const float4* qp = (const float4*)&qh[(tbase + r) * HD];
#pragma unroll
        for (int g = 0; g < 16; g++) {
            float4 q = qp[g];
            q.x = tf32r(q.x * ebc); q.y = tf32r(q.y * ebc);
            q.z = tf32r(q.z * ebc); q.w = tf32r(q.w * ebc);
            *(float4*)&qs[r * PSTR + g * 4] = q;
        }
    }
    {
        const int e = tid & 63, dg = (tid >> 6) * 16;
        const float* Sp = Sprev + (size_t)cid * HD * HD;
#pragma unroll
        for (int i = 0; i < 16; i++)
            bsK[e * PSTR + dg + i] = tf32r(Sp[(dg + i) * HD + e]);
    }
    __syncthreads();

    uint32_t a_offQ[2], a_offP[2], b_off[4];
#pragma unroll
    for (int mt = 0; mt < 2; mt++) {
        int rr = mt * 16 + ((lane >> 3) & 1) * 8 + (lane & 7);
        int cc = (lane >> 4) * 4;
        a_offQ[mt] = (uint32_t)(((w * 32 + rr) * PSTR + cc) * 4);
        a_offP[mt] = (uint32_t)((w * 32 * PSTR + rr * PSTR + cc) * 4);
    }
#pragma unroll
    for (int j = 0; j < 4; j++) {
        int rr = j * 16 + ((lane >> 4) & 1) * 8 + (lane & 7);
        int cc = ((lane >> 3) & 1) * 4;
        b_off[j] = (uint32_t)((rr * PSTR + cc) * 4);
    }
    const uint32_t sQ = (uint32_t)__cvta_generic_to_shared(qs);
    const uint32_t sK = (uint32_t)__cvta_generic_to_shared(bsK);
    const uint32_t sV = (uint32_t)__cvta_generic_to_shared(bsV);
    const uint32_t sP = (uint32_t)__cvta_generic_to_shared(Pw);

    float O[2][8][4];
#pragma unroll
    for (int mt = 0; mt < 2; mt++)
#pragma unroll
        for (int nt = 0; nt < 8; nt++)
#pragma unroll
            for (int u = 0; u < 4; u++) O[mt][nt][u] = 0.f;

#pragma unroll
    for (int ks = 0; ks < 8; ++ks) {
        const uint32_t ko = ks * 32;
        uint32_t af[2][4], bf[8][2];
#pragma unroll
        for (int mt = 0; mt < 2; mt++) LDSM_X4(af[mt], sQ + a_offQ[mt] + ko);
#pragma unroll
        for (int j = 0; j < 4; j++) {
            uint32_t t4[4];
            LDSM_X4(t4, sK + b_off[j] + ko);
            bf[2 * j][0] = t4[0]; bf[2 * j][1] = t4[1];
            bf[2 * j + 1][0] = t4[2]; bf[2 * j + 1][1] = t4[3];
        }
#pragma unroll
        for (int mt = 0; mt < 2; mt++)
#pragma unroll
            for (int nt = 0; nt < 8; nt++)
                MMA_TF32(O[mt][nt], af[mt], bf[nt]);
    }

    const int jmax = w >> 1;
    for (int j = 0; j < 4; ++j) {
        __syncthreads();
        {
            const int c = tid >> 2, cg = (tid & 3) * 16;
            const float em = expf(-bc[tbase + j * 64 + c]);
            const float4* kp = (const float4*)&kh[(tbase + j * 64 + c) * HD + cg];
#pragma unroll
            for (int ii = 0; ii < 4; ii++) {
                float4 k4 = kp[ii];
                k4.x = tf32r(k4.x * em); k4.y = tf32r(k4.y * em);
                k4.z = tf32r(k4.z * em); k4.w = tf32r(k4.w * em);
                *(float4*)&bsK[c * PSTR + cg + ii * 4] = k4;
            }
        }
        {
            const int c = tid & 63, dg = (tid >> 6) * 16;
            const float4* vp = (const float4*)&vh[(tbase + j * 64 + c) * HD + dg];
#pragma unroll
            for (int ii = 0; ii < 4; ii++) {
                float4 v4 = vp[ii];
                bsV[(dg + ii * 4 + 0) * PSTR + c] = tf32r(v4.x);
                bsV[(dg + ii * 4 + 1) * PSTR + c] = tf32r(v4.y);
                bsV[(dg + ii * 4 + 2) * PSTR + c] = tf32r(v4.z);
                bsV[(dg + ii * 4 + 3) * PSTR + c] = tf32r(v4.w);
            }
        }
        __syncthreads();

        if (j <= jmax) {
            float P[2][8][4];
#pragma unroll
            for (int mt = 0; mt < 2; mt++)
#pragma unroll
                for (int nt = 0; nt < 8; nt++)
#pragma unroll
                    for (int u = 0; u < 4; u++) P[mt][nt][u] = 0.f;
#pragma unroll
            for (int ks = 0; ks < 8; ++ks) {
                const uint32_t ko = ks * 32;
                uint32_t af[2][4], bf[8][2];
#pragma unroll
                for (int mt = 0; mt < 2; mt++)
                    LDSM_X4(af[mt], sQ + a_offQ[mt] + ko);
#pragma unroll
                for (int jj = 0; jj < 4; jj++) {
                    uint32_t t4[4];
                    LDSM_X4(t4, sK + b_off[jj] + ko);
                    bf[2 * jj][0] = t4[0]; bf[2 * jj][1] = t4[1];
                    bf[2 * jj + 1][0] = t4[2]; bf[2 * jj + 1][1] = t4[3];
                }
#pragma unroll
                for (int mt = 0; mt < 2; mt++)
#pragma unroll
                    for (int nt = 0; nt < 8; nt++)
                        MMA_TF32(P[mt][nt], af[mt], bf[nt]);
            }
            const bool diag = (j == jmax);
            const int rbase = (w & 1) * 32;
            float* Pm = Pw + w * 32 * PSTR;
#pragma unroll
            for (int mt = 0; mt < 2; mt++)
#pragma unroll
                for (int nt = 0; nt < 8; nt++)
#pragma unroll
                    for (int u = 0; u < 4; u++) {
                        int rl = mt * 16 + (lane >> 2) + ((u >> 1) << 3);
                        int cl = nt * 8 + 2 * (lane & 3) + (u & 1);
                        float val = P[mt][nt][u];
                        if (diag && (rbase + rl) < cl) val = 0.f;
                        Pm[rl * PSTR + cl] = tf32r(val);
                    }
            __syncwarp();
#pragma unroll
            for (int ks = 0; ks < 8; ++ks) {
                const uint32_t ko = ks * 32;
                uint32_t af[2][4], bf[8][2];
#pragma unroll
                for (int mt = 0; mt < 2; mt++)
                    LDSM_X4(af[mt], sP + a_offP[mt] + ko);
#pragma unroll
                for (int jj = 0; jj < 4; jj++) {
                    uint32_t t4[4];
                    LDSM_X4(t4, sV + b_off[jj] + ko);
                    bf[2 * jj][0] = t4[0]; bf[2 * jj][1] = t4[1];
                    bf[2 * jj + 1][0] = t4[2]; bf[2 * jj + 1][1] = t4[3];
                }
#pragma unroll
                for (int mt = 0; mt < 2; mt++)
#pragma unroll
                    for (int nt = 0; nt < 8; nt++)
                        MMA_TF32(O[mt][nt], af[mt], bf[nt]);
            }
        }
    }

#pragma unroll
    for (int mt = 0; mt < 2; mt++) {
        float s0 = 0.f, s1 = 0.f;
#pragma unroll
        for (int nt = 0; nt < 8; nt++) {
            s0 += O[mt][nt][0] * O[mt][nt][0] + O[mt][nt][1] * O[mt][nt][1];
            s1 += O[mt][nt][2] * O[mt][nt][2] + O[mt][nt][3] * O[mt][nt][3];
        }
        s0 += __shfl_xor_sync(0xffffffffu, s0, 1);
        s0 += __shfl_xor_sync(0xffffffffu, s0, 2);
        s1 += __shfl_xor_sync(0xffffffffu, s1, 1);
        s1 += __shfl_xor_sync(0xffffffffu, s1, 2);
        const float rr0 = rsqrtf(s0 * (1.f / (float)HD) + EPS);
        const float rr1 = rsqrtf(s1 * (1.f / (float)HD) + EPS);

        const int lr0 = w * 32 + mt * 16 + (lane >> 2);
        const size_t row0 = (size_t)b * TT + n * CC + lr0;
        const size_t row1 = row0 + 8;
#pragma unroll
        for (int nt = 0; nt < 8; nt++) {
            const int c0 = h * HD + nt * 8 + 2 * (lane & 3);
            float2 ga = *(const float2*)&gate[row0 * (4 * DD) + 3 * DD + c0];
            float2 gb = *(const float2*)&gate[row1 * (4 * DD) + 3 * DD + c0];
            float sax = ga.x / (1.f + expf(-ga.x));
            float say = ga.y / (1.f + expf(-ga.y));
            float sbx = gb.x / (1.f + expf(-gb.x));
            float sby = gb.y / (1.f + expf(-gb.y));
            *(float2*)&opre[row0 * DD + c0] = make_float2(
                tf32r(sax * O[mt][nt][0] * rr0), tf32r(say * O[mt][nt][1] * rr0));
            *(float2*)&opre[row1 * DD + c0] = make_float2(
                tf32r(sbx * O[mt][nt][2] * rr1), tf32r(sby * O[mt][nt][3] * rr1));
        }
    }
}

// ---------------- prep: round x to tf32 ----------------
__global__ __launch_bounds__(256)
void round_tf32(const float* __restrict__ in, float* __restrict__ out) {
    size_t i = ((size_t)blockIdx.x * 256 + threadIdx.x) * 4;
    float4 v = *(const float4*)(in + i);
    v.x = tf32r(v.x); v.y = tf32r(v.y); v.z = tf32r(v.z); v.w = tf32r(v.w);
    *(float4*)(out + i) = v;
}

// ---------------- prep: transpose + round 5 weights -> [N][K] (batched) ----------
__global__ __launch_bounds__(256)
void round_tr5(const float* __restrict__ Wq, const float* __restrict__ Wk,
               const float* __restrict__ Wv, const float* __restrict__ Wg,
               const float* __restrict__ Wo,
               float* __restrict__ Wf, float* __restrict__ WoT) {
    __shared__ float t[32][33];
    const float* srcs[5] = {Wq, Wk, Wv, Wg, Wo};
    const int z = blockIdx.z;
    const float* W = srcs[z];
    float* Wt = (z < 4) ? (Wf + (size_t)z * DD * DD) : WoT;
    const int bx = blockIdx.x * 32, by = blockIdx.y * 32;
    const int x = threadIdx.x & 31, y = threadIdx.x >> 5;
#pragma unroll
    for (int j = 0; j < 32; j += 8)
        t[y + j][x] = W[(size_t)(by + y + j) * DD + bx + x];
    __syncthreads();
#pragma unroll
    for (int j = 0; j < 32; j += 8)
        Wt[(size_t)(bx + y + j) * DD + by + x] = tf32r(t[x][y + j]);
}

// ---------------- skinny GEMM: gt = log_sigmoid(x @ Wgt)/16 -> (bh, t) ---------
// 64 rows/block (256 blocks): Wgt traffic 64MB -> 16MB. Thread (r, hg) computes
// 4 heads of one row; vectorized smem loads: 5 LDS.128 per 16 FMA.
__global__ __launch_bounds__(256)
void gt_gemm(const float* __restrict__ x, const float* __restrict__ Wgt,
             float* __restrict__ gtout) {
    __shared__ float xs[64][68];
    __shared__ float ws[64][20];     // stride 20: &ws[k][hg*4] stays 16B-aligned
    const int row0 = blockIdx.x * 64;
    const int tid = threadIdx.x;
    const int r  = tid >> 2;         // 0..63
    const int q4 = tid & 3;          // quarter index
    const int hg = q4 * 4;           // head group base

    float acc[4] = {0.f, 0.f, 0.f, 0.f};

    for (int kt = 0; kt < DD; kt += 64) {
        __syncthreads();
        // stage x tile: thread loads 16 floats of row r (4 x float4), coalesced
        {
            const float4* xp =
                (const float4*)&x[(size_t)(row0 + r) * DD + kt + q4 * 16];
            float4* dst = (float4*)&xs[r][q4 * 16];
            dst[0] = xp[0]; dst[1] = xp[1]; dst[2] = xp[2]; dst[3] = xp[3];
        }
        // stage Wgt tile [64][16]: thread stages 1 float4 (k = r, heads q4*4..+3)
        {
            *(float4*)&ws[r][hg] =
                *(const float4*)&Wgt[(size_t)(kt + r) * HH + hg];
        }
        __syncthreads();
#pragma unroll
        for (int kk = 0; kk < 64; kk += 4) {
            float4 a  = *(const float4*)&xs[r][kk];
            float4 w0 = *(const float4*)&ws[kk + 0][hg];
            float4 w1 = *(const float4*)&ws[kk + 1][hg];
            float4 w2 = *(const float4*)&ws[kk + 2][hg];
            float4 w3 = *(const float4*)&ws[kk + 3][hg];
            acc[0] += a.x * w0.x + a.y * w1.x + a.z * w2.x + a.w * w3.x;
            acc[1] += a.x * w0.y + a.y * w1.y + a.z * w2.y + a.w * w3.y;
            acc[2] += a.x * w0.z + a.y * w1.z + a.z * w2.z + a.w * w3.z;
            acc[3] += a.x * w0.w + a.y * w1.w + a.z * w2.w + a.w * w3.w;
        }
    }

    const int row = row0 + r;
    const int b = row / TT, t = row % TT;
#pragma unroll
    for (int j = 0; j < 4; j++) {
        float z = acc[j];
        float ls = fminf(z, 0.f) - log1pf(expf(-fabsf(z)));
        gtout[((size_t)(b * HH + hg + j)) * TT + t] = ls * (1.f / 16.f);
    }
}

// ---------------- fused rmsnorm (q,k,v) + reorder to head-major ----------
__global__ __launch_bounds__(256)
void rmsnorm_reorder3(const float* __restrict__ qkvg, float* __restrict__ qd,
                      float* __restrict__ kd, float* __restrict__ vd) {
    const int row = blockIdx.x;
    const int b = row / TT, t = row % TT;
    const int tid = threadIdx.x;
    __shared__ float red[8];
    float* dsts[3] = {qd, kd, vd};
    const float extras[3] = {0.125f, 1.f, 1.f};
#pragma unroll
    for (int part = 0; part < 3; part++) {
        float4 v = *(const float4*)&qkvg[(size_t)row * (4 * DD) + part * DD + tid * 4];
        float ss = v.x * v.x + v.y * v.y + v.z * v.z + v.w * v.w;
#pragma unroll
        for (int off = 16; off > 0; off >>= 1)
            ss += __shfl_xor_sync(0xffffffffu, ss, off);
        if ((tid & 31) == 0) red[tid >> 5] = ss;
        __syncthreads();
        float tot = red[0] + red[1] + red[2] + red[3] +
                    red[4] + red[5] + red[6] + red[7];
        float rr = rsqrtf(tot * (1.f / (float)DD) + EPS) * extras[part];
        int col = tid * 4;
        int h = col >> 6, j = col & 63;
        *(float4*)&dsts[part][((size_t)(b * HH + h) * TT + t) * HD + j] =
            make_float4(v.x * rr, v.y * rr, v.z * rr, v.w * rr);
        __syncthreads();
    }
}

// ---------------- per-chunk inclusive cumsum of gt ----------------
__global__ __launch_bounds__(256)
void cumsum_kernel(const float* __restrict__ gt, float* __restrict__ bc,
                   float* __restrict__ Bsum) {
    const int cid = blockIdx.x;
    const int bh = cid / NC, n = cid % NC;
    const int i = threadIdx.x;
    const size_t idx = (size_t)bh * TT + n * CC + i;
    __shared__ float s[CC];
    s[i] = gt[idx];
    __syncthreads();
    for (int off = 1; off < CC; off <<= 1) {
        float add = (i >= off) ? s[i - off] : 0.f;
        __syncthreads();
        s[i] += add;
        __syncthreads();
    }
    bc[idx] = s[i];
    if (i == CC - 1) Bsum[cid] = s[i];
}

// ---------------- per-chunk kv = (k * exp(B - bc))^T @ v  (64x64) ----------------
__global__ __launch_bounds__(256)
void kv_kernel(const float* __restrict__ kh, const float* __restrict__ vh,
               const float* __restrict__ bc, const float* __restrict__ Bsum,
               float* __restrict__ kv) {
    const int cid = blockIdx.x;
    const int bh = cid / NC, n = cid % NC;
    const size_t tbase = (size_t)bh * TT + n * CC;
    const int tid = threadIdx.x;
    __shared__ float ks[32][64];
    __shared__ float vs[32][64];
    const float Bn = Bsum[cid];
    const int ty = tid >> 4, tx = tid & 15;
    const int tr = tid >> 3, c8 = (tid & 7) << 3;
    float acc[4][4];
#pragma unroll
    for (int i = 0; i < 4; i++)
#pragma unroll
        for (int j = 0; j < 4; j++) acc[i][j] = 0.f;

    for (int ct = 0; ct < 8; ++ct) {
        __syncthreads();
        int trow = ct * 32 + tr;
        float e = expf(Bn - bc[tbase + trow]);
        size_t gb = (tbase + trow) * HD;
        float4 k0 = *(const float4*)&kh[gb + c8];
        float4 k1 = *(const float4*)&kh[gb + c8 + 4];
        *(float4*)&ks[tr][c8]     = make_float4(k0.x * e, k0.y * e, k0.z * e, k0.w * e);
        *(float4*)&ks[tr][c8 + 4] = make_float4(k1.x * e, k1.y * e, k1.z * e, k1.w * e);
        *(float4*)&vs[tr][c8]     = *(const float4*)&vh[gb + c8];
        *(float4*)&vs[tr][c8 + 4] = *(const float4*)&vh[gb + c8 + 4];
        __syncthreads();
#pragma unroll
        for (int kk = 0; kk < 32; ++kk) {
            float4 ka = *(const float4*)&ks[kk][ty * 4];
            float4 vb = *(const float4*)&vs[kk][tx * 4];
            float kaa[4] = {ka.x, ka.y, ka.z, ka.w};
            float vbb[4] = {vb.x, vb.y, vb.z, vb.w};
#pragma unroll
            for (int i = 0; i < 4; i++)
#pragma unroll
                for (int j = 0; j < 4; j++)
                    acc[i][j] += kaa[i] * vbb[j];
        }
    }
    size_t ob = (size_t)cid * HD * HD;
#pragma unroll
    for (int i = 0; i < 4; i++)
        *(float4*)&kv[ob + (size_t)(ty * 4 + i) * HD + tx * 4] =
            make_float4(acc[i][0], acc[i][1], acc[i][2], acc[i][3]);
}

// ---------------- sequential chunk scan ----------------
__global__ __launch_bounds__(256)
void scan_kernel(const float* __restrict__ kv, const float* __restrict__ Bsum,
                 float* __restrict__ Sprev) {
    const int bh = blockIdx.x;
    const int tid = threadIdx.x;
    float4 S[4];
#pragma unroll
    for (int u = 0; u < 4; u++) S[u] = make_float4(0.f, 0.f, 0.f, 0.f);
    for (int n = 0; n < NC; ++n) {
        size_t cb = (size_t)(bh * NC + n) * HD * HD + tid * 16;
#pragma unroll
        for (int u = 0; u < 4; u++) *(float4*)&Sprev[cb + u * 4] = S[u];
        float eB = expf(Bsum[bh * NC + n]);
#pragma unroll
        for (int u = 0; u < 4; u++) {
            float4 kvv = *(const float4*)&kv[cb + u * 4];
            S[u].x = eB * S[u].x + kvv.x;
            S[u].y = eB * S[u].y + kvv.y;
            S[u].z = eB * S[u].z + kvv.z;
            S[u].w = eB * S[u].w + kvv.w;
        }
    }
}

// ---------------- host launcher ----------------
static float* devptr(const void* symbol) {
    void* p = nullptr;
    cudaGetSymbolAddress(&p, symbol);
    return (float*)p;
}

extern "C" void kernel_launch(void* const* d_in, const int* in_sizes, int n_in,
                              void* d_out, int out_size) {
    const float* x   = (const float*)d_in[0];
    const float* Wq  = (const float*)d_in[1];
    const float* Wk  = (const float*)d_in[2];
    const float* Wv  = (const float*)d_in[3];
    const float* Wg  = (const float*)d_in[4];
    const float* Wgt = (const float*)d_in[5];
    const float* Wo  = (const float*)d_in[6];
    float* out = (float*)d_out;

    float* qkvg = devptr(g_qkvg);
    float* qhp = devptr(g_qh);
    float* khp = devptr(g_kh);
    float* vhp = devptr(g_vh);
    float* xtf = devptr(g_xtf);
    float* wf  = devptr(g_wf);
    float* wo  = devptr(g_wo);
    float* gtp = devptr(g_gt);
    float* bcp = devptr(g_bc);
    float* Bp  = devptr(g_Bsum);
    float* kvp = devptr(g_kv);
    float* Sp  = devptr(g_Sprev);

    cudaFuncSetAttribute(gemm_tf32,
        cudaFuncAttributeMaxDynamicSharedMemorySize, SMEM_GEMM);
    cudaFuncSetAttribute(attn_mma,
        cudaFuncAttributeMaxDynamicSharedMemorySize, SMEM_ATTN);

    // prep
    round_tf32<<<(BT * DD / 4) / 256, 256>>>(x, xtf);
    dim3 tg5(32, 32, 5);
    round_tr5<<<tg5, 256>>>(Wq, Wk, Wv, Wg, Wo, wf, wo);

    dim3 gfused(4 * DD / BN, BT / BM);   // (16, 128)
    gemm_tf32<<<gfused, 512, SMEM_GEMM>>>(xtf, wf, qkvg, BT, 4 * DD, DD);
    gt_gemm<<<BT / 64, 256>>>(x, Wgt, gtp);

    rmsnorm_reorder3<<<BT, 256>>>(qkvg, qhp, khp, vhp);

    cumsum_kernel<<<NCH, 256>>>(gtp, bcp, Bp);
    kv_kernel<<<NCH, 256>>>(khp, vhp, bcp, Bp, kvp);
    scan_kernel<<<BH, 256>>>(kvp, Bp, Sp);

    // xtf dead after fused GEMM: reuse as opre
    attn_mma<<<NCH, 256, SMEM_ATTN>>>(qhp, khp, vhp, bcp, Sp, qkvg, xtf);

    dim3 gout(DD / BN, BT / BM);         // (4, 128)
    gemm_tf32<<<gout, 512, SMEM_GEMM>>>(xtf, wo, out, BT, DD, DD);
}

// round 17
// speedup vs baseline: 1.0226x; 1.0036x over previous
#include <cuda_runtime.h>
#include <cuda_bf16.h>
#include <stdint.h>
#include <math.h>

// ---------------- problem constants ----------------
#define BB   2
#define TT   8192
#define DD   1024
#define HH   16
#define HD   64
#define CC   256
#define NC   (TT / CC)
#define BT   (BB * TT)          // 16384 rows
#define BH   (BB * HH)          // 32
#define NCH  (BH * NC)          // 1024
#define EPS  1e-6f

// ---------------- device scratch ----------------
__device__ float g_qkvg[BT * 4 * DD];
__device__ float g_qh[BT * DD];
__device__ float g_kh[BT * DD];
__device__ float g_vh[BT * DD];
__device__ float g_xtf[BT * DD];       // tf32-rounded x; reused later as "opre"
__device__ float g_wf[4 * DD * DD];    // tf32 TRANSPOSED fused weights [4N][K]
__device__ float g_wo[DD * DD];        // tf32 TRANSPOSED Wo [N][K]
__device__ float g_gt[BH * TT];
__device__ float g_bc[BH * TT];
__device__ float g_Bsum[NCH];
__device__ float g_kv[NCH * HD * HD];
__device__ float g_Sprev[NCH * HD * HD];

__device__ __forceinline__ float tf32r(float x) {
    uint32_t u;
    asm("cvt.rna.tf32.f32 %0, %1;" : "=r"(u) : "f"(x));
    return __uint_as_float(u);
}

#define MMA_TF32(acc, af, bf)                                              \
    asm volatile(                                                          \
        "mma.sync.aligned.m16n8k8.row.col.f32.tf32.tf32.f32 "              \
        "{%0,%1,%2,%3}, {%4,%5,%6,%7}, {%8,%9}, {%0,%1,%2,%3};\n"          \
        : "+f"((acc)[0]), "+f"((acc)[1]), "+f"((acc)[2]), "+f"((acc)[3])   \
        : "r"((af)[0]), "r"((af)[1]), "r"((af)[2]), "r"((af)[3]),          \
          "r"((bf)[0]), "r"((bf)[1]))

#define LDSM_X4(d, addr)                                                   \
    asm volatile(                                                          \
        "ldmatrix.sync.aligned.m8n8.x4.shared.b16 {%0,%1,%2,%3}, [%4];"    \
        : "=r"((d)[0]), "=r"((d)[1]), "=r"((d)[2]), "=r"((d)[3])           \
        : "r"(addr))

// ---------------- tf32 tensor-core GEMM (R10 best config): C = A @ Bt^T ----
#define BM  128
#define BN  256
#define BKK 32
#define STR 36
#define ASTG (BM * STR)
#define BSTG (BN * STR)
#define NSTAGE 3
#define SMEM_GEMM ((NSTAGE * (ASTG + BSTG)) * 4)   // 165888 B

__global__ __launch_bounds__(512, 1)
void gemm_tf32(const float* __restrict__ A, const float* __restrict__ Bt,
               float* __restrict__ C, int M, int N, int K) {
    extern __shared__ float sm[];
    float* As = sm;
    float* Bs = sm + NSTAGE * ASTG;

    const int tid  = threadIdx.x;
    const int wid  = tid >> 5, lane = tid & 31;
    const int wm   = wid >> 2, wn   = wid & 3;
    const int row0 = blockIdx.y * BM, col0 = blockIdx.x * BN;

    const int ar  = tid >> 2;
    const int akq = (tid & 3) * 8;
    const int br  = tid >> 1;
    const int bkq = (tid & 1) * 16;

    const float* Ag = A  + (size_t)(row0 + ar) * K + akq;
    const float* Bg = Bt + (size_t)(col0 + br) * K + bkq;

    uint32_t a_off[2];
#pragma unroll
    for (int mt = 0; mt < 2; mt++) {
        int r = wm * 32 + mt * 16 + ((lane >> 3) & 1) * 8 + (lane & 7);
        int c = (lane >> 4) * 4;
        a_off[mt] = (uint32_t)((r * STR + c) * 4);
    }
    uint32_t b_off[4];
#pragma unroll
    for (int j = 0; j < 4; j++) {
        int r = wn * 64 + j * 16 + ((lane >> 4) & 1) * 8 + (lane & 7);
        int c = ((lane >> 3) & 1) * 4;
        b_off[j] = (uint32_t)((r * STR + c) * 4);
    }
    const uint32_t sbA = (uint32_t)__cvta_generic_to_shared(As);
    const uint32_t sbB = (uint32_t)__cvta_generic_to_shared(Bs);

    float acc[2][8][4];
#pragma unroll
    for (int mt = 0; mt < 2; mt++)
#pragma unroll
        for (int nt = 0; nt < 8; nt++)
#pragma unroll
            for (int u = 0; u < 4; u++) acc[mt][nt][u] = 0.f;

    const int NIT = K / BKK;

#pragma unroll
    for (int s0 = 0; s0 < 2; s0++) {
        const int kt = s0 * BKK;
        uint32_t ab = (uint32_t)__cvta_generic_to_shared(
            &As[s0 * ASTG + ar * STR + akq]);
        uint32_t bb = (uint32_t)__cvta_generic_to_shared(
            &Bs[s0 * BSTG + br * STR + bkq]);
        const float* ag = Ag + kt;
        const float* bg = Bg + kt;
#pragma unroll
        for (int u = 0; u < 2; u++)
            asm volatile("cp.async.cg.shared.global [%0], [%1], 16;"
                         :: "r"(ab + u * 16), "l"(ag + u * 4));
#pragma unroll
        for (int u = 0; u < 4; u++)
            asm volatile("cp.async.cg.shared.global [%0], [%1], 16;"
                         :: "r"(bb + u * 16), "l"(bg + u * 4));
        asm volatile("cp.async.commit_group;");
    }

    int slot = 0;
    for (int it = 0; it < NIT; ++it) {
        if (it + 1 < NIT) {
            asm volatile("cp.async.wait_group 1;");
        } else {
            asm volatile("cp.async.wait_group 0;");
        }
        __syncthreads();

        if (it + 2 < NIT) {
            int ns = slot + 2; if (ns >= NSTAGE) ns -= NSTAGE;
            const int kt = (it + 2) * BKK;
            uint32_t ab = (uint32_t)__cvta_generic_to_shared(
                &As[ns * ASTG + ar * STR + akq]);
            uint32_t bb = (uint32_t)__cvta_generic_to_shared(
                &Bs[ns * BSTG + br * STR + bkq]);
            const float* ag = Ag + kt;
            const float* bg = Bg + kt;
#pragma unroll
            for (int u = 0; u < 2; u++)
                asm volatile("cp.async.cg.shared.global [%0], [%1], 16;"
                             :: "r"(ab + u * 16), "l"(ag + u * 4));
#pragma unroll
            for (int u = 0; u < 4; u++)
                asm volatile("cp.async.cg.shared.global [%0], [%1], 16;"
                             :: "r"(bb + u * 16), "l"(bg + u * 4));
            asm volatile("cp.async.commit_group;");
        }

        const uint32_t aS = sbA + slot * (ASTG * 4);
        const uint32_t bS = sbB + slot * (BSTG * 4);
#pragma unroll
        for (int ks = 0; ks < 4; ++ks) {
            const uint32_t ko = ks * 32;
            uint32_t af[2][4], bf[8][2];
#pragma unroll
            for (int mt = 0; mt < 2; mt++)
                LDSM_X4(af[mt], aS + a_off[mt] + ko);
#pragma unroll
            for (int j = 0; j < 4; j++) {
                uint32_t t4[4];
                LDSM_X4(t4, bS + b_off[j] + ko);
                bf[2 * j][0] = t4[0]; bf[2 * j][1] = t4[1];
                bf[2 * j + 1][0] = t4[2]; bf[2 * j + 1][1] = t4[3];
            }
#pragma unroll
            for (int mt = 0; mt < 2; mt++)
#pragma unroll
                for (int nt = 0; nt < 8; nt++)
                    MMA_TF32(acc[mt][nt], af[mt], bf[nt]);
        }
        if (++slot == NSTAGE) slot = 0;
    }

    const int crow = row0 + wm * 32 + (lane >> 2);
    const int ccol = col0 + wn * 64 + (lane & 3) * 2;
#pragma unroll
    for (int mt = 0; mt < 2; mt++)
#pragma unroll
        for (int nt = 0; nt < 8; nt++) {
            float* p0 = C + (size_t)(crow + mt * 16) * N + ccol + nt * 8;
            float* p1 = p0 + (size_t)8 * N;
            *(float2*)p0 = make_float2(acc[mt][nt][0], acc[mt][nt][1]);
            *(float2*)p1 = make_float2(acc[mt][nt][2], acc[mt][nt][3]);
        }
}

// ---------------- tensorized attention, Q fragments cached in registers ---------
#define PSTR 68
#define SMEM_ATTN ((256 * PSTR + 64 * PSTR + 64 * PSTR + 8 * 32 * PSTR) * 4)

__global__ __launch_bounds__(256, 1)
void attn_mma(const float* __restrict__ qh, const float* __restrict__ kh,
              const float* __restrict__ vh, const float* __restrict__ bc,
              const float* __restrict__ Sprev, const float* __restrict__ gate,
              float* __restrict__ opre) {
    extern __shared__ float sm[];
    float* qs  = sm;
    float* bsK = qs + 256 * PSTR;
    float* bsV = bsK + 64 * PSTR;
    float* Pw  = bsV + 64 * PSTR;

    const int cid = blockIdx.x;
    const int bh = cid / NC, n = cid % NC;
    const int b = bh / HH, h = bh % HH;
    const int tid = threadIdx.x;
    const int w = tid >> 5, lane = tid & 31;
    const size_t tbase = (size_t)bh * TT + n * CC;

    {
        const int r = tid;
        const float ebc = expf(bc[tbase + r]);
        const float4* qp = (const float4*)&qh[(tbase + r) * HD];
#pragma unroll
        for (int g = 0; g < 16; g++) {
            float4 q = qp[g];
            q.x = tf32r(q.x * ebc); q.y = tf32r(q.y * ebc);
            q.z = tf32r(q.z * ebc); q.w = tf32r(q.w * ebc);
            *(float4*)&qs[r * PSTR + g * 4] = q;
        }
    }
    {
        const int e = tid & 63, dg = (tid >> 6) * 16;
        const float* Sp = Sprev + (size_t)cid * HD * HD;
#pragma unroll
        for (int i = 0; i < 16; i++)
            bsK[e * PSTR + dg + i] = tf32r(Sp[(dg + i) * HD + e]);
    }
    __syncthreads();

    uint32_t a_offQ[2], a_offP[2], b_off[4];
#pragma unroll
    for (int mt = 0; mt < 2; mt++) {
        int rr = mt * 16 + ((lane >> 3) & 1) * 8 + (lane & 7);
        int cc = (lane >> 4) * 4;
        a_offQ[mt] = (uint32_t)(((w * 32 + rr) * PSTR + cc) * 4);
        a_offP[mt] = (uint32_t)((w * 32 * PSTR + rr * PSTR + cc) * 4);
    }
#pragma unroll
    for (int j = 0; j < 4; j++) {
        int rr = j * 16 + ((lane >> 4) & 1) * 8 + (lane & 7);
        int cc = ((lane >> 3) & 1) * 4;
        b_off[j] = (uint32_t)((rr * PSTR + cc) * 4);
    }
    const uint32_t sQ = (uint32_t)__cvta_generic_to_shared(qs);
    const uint32_t sK = (uint32_t)__cvta_generic_to_shared(bsK);
    const uint32_t sV = (uint32_t)__cvta_generic_to_shared(bsV);
    const uint32_t sP = (uint32_t)__cvta_generic_to_shared(Pw);

    // ---- load Q fragments ONCE into registers (qs is write-once) ----
    uint32_t qf[8][2][4];
#pragma unroll
    for (int ks = 0; ks < 8; ++ks)
#pragma unroll
        for (int mt = 0; mt < 2; mt++)
            LDSM_X4(qf[ks][mt], sQ + a_offQ[mt] + ks * 32);

    float O[2][8][4];
#pragma unroll
    for (int mt = 0; mt < 2; mt++)
#pragma unroll
        for (int nt = 0; nt < 8; nt++)
#pragma unroll
            for (int u = 0; u < 4; u++) O[mt][nt][u] = 0.f;

    // ---- cross term: O += Q @ STs^T ----
#pragma unroll
    for (int ks = 0; ks < 8; ++ks) {
        const uint32_t ko = ks * 32;
        uint32_t bf[8][2];
#pragma unroll
        for (int j = 0; j < 4; j++) {
            uint32_t t4[4];
            LDSM_X4(t4, sK + b_off[j] + ko);
            bf[2 * j][0] = t4[0]; bf[2 * j][1] = t4[1];
            bf[2 * j + 1][0] = t4[2]; bf[2 * j + 1][1] = t4[3];
        }
#pragma unroll
        for (int mt = 0; mt < 2; mt++)
#pragma unroll
            for (int nt = 0; nt < 8; nt++)
                MMA_TF32(O[mt][nt], qf[ks][mt], bf[nt]);
    }

    const int jmax = w >> 1;
    for (int j = 0; j < 4; ++j) {
        __syncthreads();
        {
            const int c = tid >> 2, cg = (tid & 3) * 16;
            const float em = expf(-bc[tbase + j * 64 + c]);
            const float4* kp = (const float4*)&kh[(tbase + j * 64 + c) * HD + cg];
#pragma unroll
            for (int ii = 0; ii < 4; ii++) {
                float4 k4 = kp[ii];
                k4.x = tf32r(k4.x * em); k4.y = tf32r(k4.y * em);
                k4.z = tf32r(k4.z * em); k4.w = tf32r(k4.w * em);
                *(float4*)&bsK[c * PSTR + cg + ii * 4] = k4;
            }
        }
        {
            const int c = tid & 63, dg = (tid >> 6) * 16;
            const float4* vp = (const float4*)&vh[(tbase + j * 64 + c) * HD + dg];
#pragma unroll
            for (int ii = 0; ii < 4; ii++) {
                float4 v4 = vp[ii];
                bsV[(dg + ii * 4 + 0) * PSTR + c] = tf32r(v4.x);
                bsV[(dg + ii * 4 + 1) * PSTR + c] = tf32r(v4.y);
                bsV[(dg + ii * 4 + 2) * PSTR + c] = tf32r(v4.z);
                bsV[(dg + ii * 4 + 3) * PSTR + c] = tf32r(v4.w);
            }
        }
        __syncthreads();

        if (j <= jmax) {
            float P[2][8][4];
#pragma unroll
            for (int mt = 0; mt < 2; mt++)
#pragma unroll
                for (int nt = 0; nt < 8; nt++)
#pragma unroll
                    for (int u = 0; u < 4; u++) P[mt][nt][u] = 0.f;
#pragma unroll
            for (int ks = 0; ks < 8; ++ks) {
                const uint32_t ko = ks * 32;
                uint32_t bf[8][2];
#pragma unroll
                for (int jj = 0; jj < 4; jj++) {
                    uint32_t t4[4];
                    LDSM_X4(t4, sK + b_off[jj] + ko);
                    bf[2 * jj][0] = t4[0]; bf[2 * jj][1] = t4[1];
                    bf[2 * jj + 1][0] = t4[2]; bf[2 * jj + 1][1] = t4[3];
                }
#pragma unroll
                for (int mt = 0; mt < 2; mt++)
#pragma unroll
                    for (int nt = 0; nt < 8; nt++)
                        MMA_TF32(P[mt][nt], qf[ks][mt], bf[nt]);
            }
            const bool diag = (j == jmax);
            const int rbase = (w & 1) * 32;
            float* Pm = Pw + w * 32 * PSTR;
#pragma unroll
            for (int mt = 0; mt < 2; mt++)
#pragma unroll
                for (int nt = 0; nt < 8; nt++)
#pragma unroll
                    for (int u = 0; u < 4; u++) {
                        int rl = mt * 16 + (lane >> 2) + ((u >> 1) << 3);
                        int cl = nt * 8 + 2 * (lane & 3) + (u & 1);
                        float val = P[mt][nt][u];
                        if (diag && (rbase + rl) < cl) val = 0.f;
                        Pm[rl * PSTR + cl] = tf32r(val);
                    }
            __syncwarp();
#pragma unroll
            for (int ks = 0; ks < 8; ++ks) {
                const uint32_t ko = ks * 32;
                uint32_t af[2][4], bf[8][2];
#pragma unroll
                for (int mt = 0; mt < 2; mt++)
                    LDSM_X4(af[mt], sP + a_offP[mt] + ko);
#pragma unroll
                for (int jj = 0; jj < 4; jj++) {
                    uint32_t t4[4];
                    LDSM_X4(t4, sV + b_off[jj] + ko);
                    bf[2 * jj][0] = t4[0]; bf[2 * jj][1] = t4[1];
                    bf[2 * jj + 1][0] = t4[2]; bf[2 * jj + 1][1] = t4[3];
                }
#pragma unroll
                for (int mt = 0; mt < 2; mt++)
#pragma unroll
                    for (int nt = 0; nt < 8; nt++)
                        MMA_TF32(O[mt][nt], af[mt], bf[nt]);
            }
        }
    }

#pragma unroll
    for (int mt = 0; mt < 2; mt++) {
        float s0 = 0.f, s1 = 0.f;
#pragma unroll
        for (int nt = 0; nt < 8; nt++) {
            s0 += O[mt][nt][0] * O[mt][nt][0] + O[mt][nt][1] * O[mt][nt][1];
            s1 += O[mt][nt][2] * O[mt][nt][2] + O[mt][nt][3] * O[mt][nt][3];
        }
        s0 += __shfl_xor_sync(0xffffffffu, s0, 1);
        s0 += __shfl_xor_sync(0xffffffffu, s0, 2);
        s1 += __shfl_xor_sync(0xffffffffu, s1, 1);
        s1 += __shfl_xor_sync(0xffffffffu, s1, 2);
        const float rr0 = rsqrtf(s0 * (1.f / (float)HD) + EPS);
        const float rr1 = rsqrtf(s1 * (1.f / (float)HD) + EPS);

        const int lr0 = w * 32 + mt * 16 + (lane >> 2);
        const size_t row0 = (size_t)b * TT + n * CC + lr0;
        const size_t row1 = row0 + 8;
#pragma unroll
        for (int nt = 0; nt < 8; nt++) {
            const int c0 = h * HD + nt * 8 + 2 * (lane & 3);
            float2 ga = *(const float2*)&gate[row0 * (4 * DD) + 3 * DD + c0];
            float2 gb = *(const float2*)&gate[row1 * (4 * DD) + 3 * DD + c0];
            float sax = ga.x / (1.f + expf(-ga.x));
            float say = ga.y / (1.f + expf(-ga.y));
            float sbx = gb.x / (1.f + expf(-gb.x));
            float sby = gb.y / (1.f + expf(-gb.y));
            *(float2*)&opre[row0 * DD + c0] = make_float2(
                tf32r(sax * O[mt][nt][0] * rr0), tf32r(say * O[mt][nt][1] * rr0));
            *(float2*)&opre[row1 * DD + c0] = make_float2(
                tf32r(sbx * O[mt][nt][2] * rr1), tf32r(sby * O[mt][nt][3] * rr1));
        }
    }
}

// ---------------- prep: round x to tf32 ----------------
__global__ __launch_bounds__(256)
void round_tf32(const float* __restrict__ in, float* __restrict__ out) {
    size_t i = ((size_t)blockIdx.x * 256 + threadIdx.x) * 4;
    float4 v = *(const float4*)(in + i);
    v.x = tf32r(v.x); v.y = tf32r(v.y); v.z = tf32r(v.z); v.w = tf32r(v.w);
    *(float4*)(out + i) = v;
}

// ---------------- prep: transpose + round 5 weights -> [N][K] (batched) ----------
__global__ __launch_bounds__(256)
void round_tr5(const float* __restrict__ Wq, const float* __restrict__ Wk,
               const float* __restrict__ Wv, const float* __restrict__ Wg,
               const float* __restrict__ Wo,
               float* __restrict__ Wf, float* __restrict__ WoT) {
    __shared__ float t[32][33];
    const float* srcs[5] = {Wq, Wk, Wv, Wg, Wo};
    const int z = blockIdx.z;
    const float* W = srcs[z];
    float* Wt = (z < 4) ? (Wf + (size_t)z * DD * DD) : WoT;
    const int bx = blockIdx.x * 32, by = blockIdx.y * 32;
    const int x = threadIdx.x & 31, y = threadIdx.x >> 5;
#pragma unroll
    for (int j = 0; j < 32; j += 8)
        t[y + j][x] = W[(size_t)(by + y + j) * DD + bx + x];
    __syncthreads();
#pragma unroll
    for (int j = 0; j < 32; j += 8)
        Wt[(size_t)(bx + y + j) * DD + by + x] = tf32r(t[x][y + j]);
}

// ---------------- skinny GEMM: gt = log_sigmoid(x @ Wgt)/16 -> (bh, t) ---------
__global__ __launch_bounds__(256)
void gt_gemm(const float* __restrict__ x, const float* __restrict__ Wgt,
             float* __restrict__ gtout) {
    __shared__ float xs[64][68];
    __shared__ float ws[64][20];
    const int row0 = blockIdx.x * 64;
    const int tid = threadIdx.x;
    const int r  = tid >> 2;
    const int q4 = tid & 3;
    const int hg = q4 * 4;

    float acc[4] = {0.f, 0.f, 0.f, 0.f};

    for (int kt = 0; kt < DD; kt += 64) {
        __syncthreads();
        {
            const float4* xp =
                (const float4*)&x[(size_t)(row0 + r) * DD + kt + q4 * 16];
            float4* dst = (float4*)&xs[r][q4 * 16];
            dst[0] = xp[0]; dst[1] = xp[1]; dst[2] = xp[2]; dst[3] = xp[3];
        }
        {
            *(float4*)&ws[r][hg] =
                *(const float4*)&Wgt[(size_t)(kt + r) * HH + hg];
        }
        __syncthreads();
#pragma unroll
        for (int kk = 0; kk < 64; kk += 4) {
            float4 a  = *(const float4*)&xs[r][kk];
            float4 w0 = *(const float4*)&ws[kk + 0][hg];
            float4 w1 = *(const float4*)&ws[kk + 1][hg];
            float4 w2 = *(const float4*)&ws[kk + 2][hg];
            float4 w3 = *(const float4*)&ws[kk + 3][hg];
            acc[0] += a.x * w0.x + a.y * w1.x + a.z * w2.x + a.w * w3.x;
            acc[1] += a.x * w0.y + a.y * w1.y + a.z * w2.y + a.w * w3.y;
            acc[2] += a.x * w0.z + a.y * w1.z + a.z * w2.z + a.w * w3.z;
            acc[3] += a.x * w0.w + a.y * w1.w + a.z * w2.w + a.w * w3.w;
        }
    }

    const int row = row0 + r;
    const int b = row / TT, t = row % TT;
#pragma unroll
    for (int j = 0; j < 4; j++) {
        float z = acc[j];
        float ls = fminf(z, 0.f) - log1pf(expf(-fabsf(z)));
        gtout[((size_t)(b * HH + hg + j)) * TT + t] = ls * (1.f / 16.f);
    }
}

// ---------------- fused rmsnorm (q,k,v) + reorder to head-major ----------
__global__ __launch_bounds__(256)
void rmsnorm_reorder3(const float* __restrict__ qkvg, float* __restrict__ qd,
                      float* __restrict__ kd, float* __restrict__ vd) {
    const int row = blockIdx.x;
    const int b = row / TT, t = row % TT;
    const int tid = threadIdx.x;
    __shared__ float red[8];
    float* dsts[3] = {qd, kd, vd};
    const float extras[3] = {0.125f, 1.f, 1.f};
#pragma unroll
    for (int part = 0; part < 3; part++) {
        float4 v = *(const float4*)&qkvg[(size_t)row * (4 * DD) + part * DD + tid * 4];
        float ss = v.x * v.x + v.y * v.y + v.z * v.z + v.w * v.w;
#pragma unroll
        for (int off = 16; off > 0; off >>= 1)
            ss += __shfl_xor_sync(0xffffffffu, ss, off);
        if ((tid & 31) == 0) red[tid >> 5] = ss;
        __syncthreads();
        float tot = red[0] + red[1] + red[2] + red[3] +
                    red[4] + red[5] + red[6] + red[7];
        float rr = rsqrtf(tot * (1.f / (float)DD) + EPS) * extras[part];
        int col = tid * 4;
        int h = col >> 6, j = col & 63;
        *(float4*)&dsts[part][((size_t)(b * HH + h) * TT + t) * HD + j] =
            make_float4(v.x * rr, v.y * rr, v.z * rr, v.w * rr);
        __syncthreads();
    }
}

// ---------------- per-chunk inclusive cumsum of gt ----------------
__global__ __launch_bounds__(256)
void cumsum_kernel(const float* __restrict__ gt, float* __restrict__ bc,
                   float* __restrict__ Bsum) {
    const int cid = blockIdx.x;
    const int bh = cid / NC, n = cid % NC;
    const int i = threadIdx.x;
    const size_t idx = (size_t)bh * TT + n * CC + i;
    __shared__ float s[CC];
    s[i] = gt[idx];
    __syncthreads();
    for (int off = 1; off < CC; off <<= 1) {
        float add = (i >= off) ? s[i - off] : 0.f;
        __syncthreads();
        s[i] += add;
        __syncthreads();
    }
    bc[idx] = s[i];
    if (i == CC - 1) Bsum[cid] = s[i];
}

// ---------------- per-chunk kv = (k * exp(B - bc))^T @ v  (64x64) ----------------
__global__ __launch_bounds__(256)
void kv_kernel(const float* __restrict__ kh, const float* __restrict__ vh,
               const float* __restrict__ bc, const float* __restrict__ Bsum,
               float* __restrict__ kv) {
    const int cid = blockIdx.x;
    const int bh = cid / NC, n = cid % NC;
    const size_t tbase = (size_t)bh * TT + n * CC;
    const int tid = threadIdx.x;
    __shared__ float ks[32][64];
    __shared__ float vs[32][64];
    const float Bn = Bsum[cid];
    const int ty = tid >> 4, tx = tid & 15;
    const int tr = tid >> 3, c8 = (tid & 7) << 3;
    float acc[4][4];
#pragma unroll
    for (int i = 0; i < 4; i++)
#pragma unroll
        for (int j = 0; j < 4; j++) acc[i][j] = 0.f;

    for (int ct = 0; ct < 8; ++ct) {
        __syncthreads();
        int trow = ct * 32 + tr;
        float e = expf(Bn - bc[tbase + trow]);
        size_t gb = (tbase + trow) * HD;
        float4 k0 = *(const float4*)&kh[gb + c8];
        float4 k1 = *(const float4*)&kh[gb + c8 + 4];
        *(float4*)&ks[tr][c8]     = make_float4(k0.x * e, k0.y * e, k0.z * e, k0.w * e);
        *(float4*)&ks[tr][c8 + 4] = make_float4(k1.x * e, k1.y * e, k1.z * e, k1.w * e);
        *(float4*)&vs[tr][c8]     = *(const float4*)&vh[gb + c8];
        *(float4*)&vs[tr][c8 + 4] = *(const float4*)&vh[gb + c8 + 4];
        __syncthreads();
#pragma unroll
        for (int kk = 0; kk < 32; ++kk) {
            float4 ka = *(const float4*)&ks[kk][ty * 4];
            float4 vb = *(const float4*)&vs[kk][tx * 4];
            float kaa[4] = {ka.x, ka.y, ka.z, ka.w};
            float vbb[4] = {vb.x, vb.y, vb.z, vb.w};
#pragma unroll
            for (int i = 0; i < 4; i++)
#pragma unroll
                for (int j = 0; j < 4; j++)
                    acc[i][j] += kaa[i] * vbb[j];
        }
    }
    size_t ob = (size_t)cid * HD * HD;
#pragma unroll
    for (int i = 0; i < 4; i++)
        *(float4*)&kv[ob + (size_t)(ty * 4 + i) * HD + tx * 4] =
            make_float4(acc[i][0], acc[i][1], acc[i][2], acc[i][3]);
}

// ---------------- sequential chunk scan ----------------
__global__ __launch_bounds__(256)
void scan_kernel(const float* __restrict__ kv, const float* __restrict__ Bsum,
                 float* __restrict__ Sprev) {
    const int bh = blockIdx.x;
    const int tid = threadIdx.x;
    float4 S[4];
#pragma unroll
    for (int u = 0; u < 4; u++) S[u] = make_float4(0.f, 0.f, 0.f, 0.f);
    for (int n = 0; n < NC; ++n) {
        size_t cb = (size_t)(bh * NC + n) * HD * HD + tid * 16;
#pragma unroll
        for (int u = 0; u < 4; u++) *(float4*)&Sprev[cb + u * 4] = S[u];
        float eB = expf(Bsum[bh * NC + n]);
#pragma unroll
        for (int u = 0; u < 4; u++) {
            float4 kvv = *(const float4*)&kv[cb + u * 4];
            S[u].x = eB * S[u].x + kvv.x;
            S[u].y = eB * S[u].y + kvv.y;
            S[u].z = eB * S[u].z + kvv.z;
            S[u].w = eB * S[u].w + kvv.w;
        }
    }
}

// ---------------- host launcher ----------------
static float* devptr(const void* symbol) {
    void* p = nullptr;
    cudaGetSymbolAddress(&p, symbol);
    return (float*)p;
}

extern "C" void kernel_launch(void* const* d_in, const int* in_sizes, int n_in,
                              void* d_out, int out_size) {
    const float* x   = (const float*)d_in[0];
    const float* Wq  = (const float*)d_in[1];
    const float* Wk  = (const float*)d_in[2];
    const float* Wv  = (const float*)d_in[3];
    const float* Wg  = (const float*)d_in[4];
    const float* Wgt = (const float*)d_in[5];
    const float* Wo  = (const float*)d_in[6];
    float* out = (float*)d_out;

    float* qkvg = devptr(g_qkvg);
    float* qhp = devptr(g_qh);
    float* khp = devptr(g_kh);
    float* vhp = devptr(g_vh);
    float* xtf = devptr(g_xtf);
    float* wf  = devptr(g_wf);
    float* wo  = devptr(g_wo);
    float* gtp = devptr(g_gt);
    float* bcp = devptr(g_bc);
    float* Bp  = devptr(g_Bsum);
    float* kvp = devptr(g_kv);
    float* Sp  = devptr(g_Sprev);

    cudaFuncSetAttribute(gemm_tf32,
        cudaFuncAttributeMaxDynamicSharedMemorySize, SMEM_GEMM);
    cudaFuncSetAttribute(attn_mma,
        cudaFuncAttributeMaxDynamicSharedMemorySize, SMEM_ATTN);

    // prep
    round_tf32<<<(BT * DD / 4) / 256, 256>>>(x, xtf);
    dim3 tg5(32, 32, 5);
    round_tr5<<<tg5, 256>>>(Wq, Wk, Wv, Wg, Wo, wf, wo);

    dim3 gfused(4 * DD / BN, BT / BM);   // (16, 128)
    gemm_tf32<<<gfused, 512, SMEM_GEMM>>>(xtf, wf, qkvg, BT, 4 * DD, DD);
    gt_gemm<<<BT / 64, 256>>>(x, Wgt, gtp);

    rmsnorm_reorder3<<<BT, 256>>>(qkvg, qhp, khp, vhp);

    cumsum_kernel<<<NCH, 256>>>(gtp, bcp, Bp);
    kv_kernel<<<NCH, 256>>>(khp, vhp, bcp, Bp, kvp);
    scan_kernel<<<BH, 256>>>(kvp, Bp, Sp);

    // xtf dead after fused GEMM: reuse as opre
    attn_mma<<<NCH, 256, SMEM_ATTN>>>(qhp, khp, vhp, bcp, Sp, qkvg, xtf);

    dim3 gout(DD / BN, BT / BM);         // (4, 128)
    gemm_tf32<<<gout, 512, SMEM_GEMM>>>(xtf, wo, out, BT, DD, DD);
}